// round 6
// baseline (speedup 1.0000x reference)
#include <cuda_runtime.h>

// MinimalRNN scan via chunked A/B decomposition with a fast carry chain.
//   h_t = exp(lc[t-1]) * h_{t-1} + exp(lv[t]),  h_0 = exp(lv[0])
// Chunk-local:  h_{s0+i} = A_i * h_{s0} + B_i   (A_i, B_i carry-independent)
// All loads + local exp-scan proceed without waiting; only the fixup stores
// wait on the upstream carry. Outgoing carry publishes IMMEDIATELY on h0
// arrival (before fixup stores). acq/rel flag ops instead of full fences.
// LL=32 keeps regs ~100 -> 5 blocks/SM residency (vs 3 at LL=64).
// Flags reset by their single consumer -> graph-replay safe.

#define BB 16
#define TT 4096
#define HH 1024
#define CC 128
#define LL (TT / CC)          // 32 steps per chunk
#define NCH (BB * HH)         // 16384 channels
#define NCOL (NCH / 128)      // 128 block-columns
#define NSTRIP (NCH / 32)     // 512 warp strips

__device__ float g_carry[(CC - 1) * NCH];
__device__ int   g_flag[(CC - 1) * NSTRIP];   // zero-init (.bss)

__global__ void __launch_bounds__(128, 5)
minrnn_ab_kernel(const float* __restrict__ lc,   // (B, T, H)
                 const float* __restrict__ lv,   // (B, T+1, H)
                 float* __restrict__ out)        // (B, T, H)
{
    const int chunk = blockIdx.x >> 7;            // chunk-major ordering
    const int col   = blockIdx.x & 127;
    const int ch    = col * 128 + threadIdx.x;    // channel 0..16383
    const int strip = ch >> 5;
    const int lane  = threadIdx.x & 31;
    const int b     = ch >> 10;
    const int h     = ch & (HH - 1);
    const int s0    = chunk * LL;

    const float* lcp  = lc + b * (TT * HH) + s0 * HH + h;             // lc[s0+i]
    const float* lvp2 = lv + b * ((TT + 1) * HH) + (s0 + 1) * HH + h; // lv[s0+i+1]
    float*       op   = out + b * (TT * HH) + s0 * HH + h;            // out step s0+i

    // ---- Phase 1: load the whole chunk (64 independent LDGs, max MLP) ----
    float cc[LL], vv[LL];
#pragma unroll
    for (int i = 0; i < LL; i++) {
        cc[i] = __ldcs(lcp + i * HH);
        vv[i] = __ldcs(lvp2 + i * HH);
    }

    // ---- Phase 2: carry-independent local scan.  cc[i] <- A_i, vv[i] <- B_i
    float A = 1.0f, Bv = 0.0f;
#pragma unroll
    for (int i = 0; i < LL; i++) {
        const float e = __expf(cc[i]);
        A *= e;
        Bv = fmaf(e, Bv, __expf(vv[i]));
        cc[i] = A;
        vv[i] = Bv;
    }

    // ---- Phase 3: acquire incoming state h_{s0} ----
    float h0;
    if (chunk == 0) {
        h0 = __expf(__ldg(lv + b * ((TT + 1) * HH) + h));   // exp(lv[b,0,h])
    } else {
        int* flg = &g_flag[(chunk - 1) * NSTRIP + strip];
        if (lane == 0) {
            int f;
            asm volatile("ld.global.acquire.gpu.b32 %0, [%1];"
                         : "=r"(f) : "l"(flg));
            while (f == 0) {
                __nanosleep(32);
                asm volatile("ld.global.acquire.gpu.b32 %0, [%1];"
                             : "=r"(f) : "l"(flg));
            }
        }
        __syncwarp();
        h0 = __ldcg(&g_carry[(chunk - 1) * NCH + ch]);
        if (lane == 0) *flg = 0;                             // reset for replay
    }

    // ---- Phase 4: publish outgoing carry FIRST (shortest possible hop) ----
    if (chunk < CC - 1) {
        __stcg(&g_carry[chunk * NCH + ch], fmaf(A, h0, Bv)); // A,Bv = last A/B
        __syncwarp();
        if (lane == 0) {
            asm volatile("st.global.release.gpu.b32 [%0], %1;"
                         :: "l"(&g_flag[chunk * NSTRIP + strip]), "r"(1));
        }
    }

    // ---- Phase 5: fixup + store (off the critical chain) ----
#pragma unroll
    for (int i = 0; i < LL; i++) {
        __stcs(op + i * HH, fmaf(cc[i], h0, vv[i]));
    }
}

extern "C" void kernel_launch(void* const* d_in, const int* in_sizes, int n_in,
                              void* d_out, int out_size)
{
    const float* log_coeffs = (const float*)d_in[0];   // (B, T, H)
    const float* log_values = (const float*)d_in[1];   // (B, T+1, H)
    float*       out        = (float*)d_out;           // (B, T, H)

    const int blocks = CC * NCOL;      // 128 * 128 = 16384, chunk-major
    minrnn_ab_kernel<<<blocks, 128>>>(log_coeffs, log_values, out);
}

// round 7
// speedup vs baseline: 2.2159x; 2.2159x over previous
#include <cuda_runtime.h>

// MinimalRNN scan via chunked A/B decomposition + DECOUPLED LOOKBACK.
//   h_t = exp(lc[t-1]) * h_{t-1} + exp(lv[t]),  h_0 = exp(lv[0])
// Chunk-local:  h_{s0+i} = A_i * h_{s0} + B_i.
// Each block publishes its local aggregate (A,B) -> flag=AGG immediately
// after the (carry-independent) local scan. Consumers compute their own
// incoming state by composing predecessors' aggregates backwards, stopping
// early at an INCLUSIVE entry (stored as (0, h_end): same affine form, so
// a racy AGG-flag/INC-pair read is still correct; pairs are atomic 8B).
// No serial inclusive chain -> waves only wait on parallel-phase results.
// A tiny cleanup kernel re-zeroes flags for graph replay.

#define BB 16
#define TT 4096
#define HH 1024
#define CC 128
#define LL (TT / CC)          // 32 steps per chunk
#define NCH (BB * HH)         // 16384 channels
#define NCOL (NCH / 128)      // 128 block-columns
#define NSTRIP (NCH / 32)     // 512 warp strips

__device__ float2 g_pair[CC * NCH];          // (A,B) aggregate or (0,h_end)
__device__ int    g_flag[CC * NSTRIP];       // 0=invalid 1=AGG 2=INC (.bss)

__global__ void __launch_bounds__(128, 6)
minrnn_lookback_kernel(const float* __restrict__ lc,   // (B, T, H)
                       const float* __restrict__ lv,   // (B, T+1, H)
                       float* __restrict__ out)        // (B, T, H)
{
    const int chunk = blockIdx.x >> 7;            // chunk-major ordering
    const int col   = blockIdx.x & 127;
    const int ch    = col * 128 + threadIdx.x;    // channel 0..16383
    const int strip = ch >> 5;                    // warp-uniform
    const int lane  = threadIdx.x & 31;
    const int b     = ch >> 10;
    const int h     = ch & (HH - 1);
    const int s0    = chunk * LL;

    const float* lcp  = lc + b * (TT * HH) + s0 * HH + h;
    const float* lvp2 = lv + b * ((TT + 1) * HH) + (s0 + 1) * HH + h;
    float*       op   = out + b * (TT * HH) + s0 * HH + h;

    // ---- Phase 1: load whole chunk (64 independent LDGs, max MLP) ----
    float cc[LL], vv[LL];
#pragma unroll
    for (int i = 0; i < LL; i++) {
        cc[i] = __ldcs(lcp + i * HH);
        vv[i] = __ldcs(lvp2 + i * HH);
    }

    // ---- Phase 2: carry-independent local scan. cc[i]<-A_i, vv[i]<-B_i ----
    float A = 1.0f, Bv = 0.0f;
#pragma unroll
    for (int i = 0; i < LL; i++) {
        const float e = __expf(cc[i]);
        A *= e;
        Bv = fmaf(e, Bv, __expf(vv[i]));
        cc[i] = A;
        vv[i] = Bv;
    }

    // ---- Phase 3: publish local AGGREGATE (no waiting!) ----
    if (chunk > 0 && chunk < CC - 1) {
        __stcg(&g_pair[chunk * NCH + ch], make_float2(A, Bv));
        __syncwarp();
        if (lane == 0) {
            asm volatile("st.global.release.gpu.b32 [%0], %1;"
                         :: "l"(&g_flag[chunk * NSTRIP + strip]), "r"(1));
        }
    }

    // ---- Phase 4: obtain incoming state h_in via lookback ----
    float h_in;
    if (chunk == 0) {
        h_in = __expf(__ldg(lv + b * ((TT + 1) * HH) + h));   // exp(lv[b,0,h])
    } else {
        float Aacc = 1.0f, Bacc = 0.0f;
        int p = chunk - 1;
        for (;;) {
            int f;
            const int* fp = &g_flag[p * NSTRIP + strip];
            for (;;) {
                asm volatile("ld.global.acquire.gpu.b32 %0, [%1];"
                             : "=r"(f) : "l"(fp));
                if (f) break;
                __nanosleep(32);
            }
            const float2 e = __ldcg(&g_pair[p * NCH + ch]);   // atomic 8B
            if (f == 2) {                       // INCLUSIVE: e.y = h_end_p
                h_in = fmaf(Aacc, e.y, Bacc);
                break;
            }
            Bacc = fmaf(Aacc, e.y, Bacc);       // compose aggregate
            Aacc *= e.x;
            p--;                                // chunk 0 is always INC
        }
    }

    // ---- Phase 5: upgrade own entry to INCLUSIVE (shortcut for others) ----
    if (chunk < CC - 1) {
        __stcg(&g_pair[chunk * NCH + ch], make_float2(0.0f, fmaf(A, h_in, Bv)));
        __syncwarp();
        if (lane == 0) {
            asm volatile("st.global.release.gpu.b32 [%0], %1;"
                         :: "l"(&g_flag[chunk * NSTRIP + strip]), "r"(2));
        }
    }

    // ---- Phase 6: fixup + store (independent) ----
#pragma unroll
    for (int i = 0; i < LL; i++) {
        __stcs(op + i * HH, fmaf(cc[i], h_in, vv[i]));
    }
}

// Re-zero flags so the next graph replay starts clean.
__global__ void minrnn_cleanup_kernel()
{
    const int i = blockIdx.x * blockDim.x + threadIdx.x;
    if (i < CC * NSTRIP) g_flag[i] = 0;
}

extern "C" void kernel_launch(void* const* d_in, const int* in_sizes, int n_in,
                              void* d_out, int out_size)
{
    const float* log_coeffs = (const float*)d_in[0];   // (B, T, H)
    const float* log_values = (const float*)d_in[1];   // (B, T+1, H)
    float*       out        = (float*)d_out;           // (B, T, H)

    const int blocks = CC * NCOL;      // 128 * 128 = 16384, chunk-major
    minrnn_lookback_kernel<<<blocks, 128>>>(log_coeffs, log_values, out);

    const int n = CC * NSTRIP;         // 65536 flags
    minrnn_cleanup_kernel<<<(n + 255) / 256, 256>>>();
}

// round 8
// speedup vs baseline: 3.2046x; 1.4462x over previous
#include <cuda_runtime.h>

// MinimalRNN scan: chunked A/B decomposition + decoupled lookback with
// PAYLOAD-ENCODED descriptors (single 8-byte relaxed atomic per entry).
//   h_t = exp(lc[t-1]) * h_{t-1} + exp(lv[t]),  h_0 = exp(lv[0])
// Chunk-local:  h_{s0+i} = A_i * h_{s0} + B_i  (carry-independent).
// Descriptor entry per (chunk, channel), packed (A,B) into u64:
//   u == 0          -> not published      (A>0 and h_end>0 => never packs to 0;
//                                          .bss zero-init is therefore valid)
//   A == 0          -> INCLUSIVE, B = h_end
//   A  > 0          -> AGGREGATE (A >= e^-32 ~ 1.3e-14, distinct from 0)
// One relaxed 8B load per lookback hop (payload IS the flag -> no fences),
// per-lane resolution (no lane-0 serialization), prefetch of predecessor-1
// pipelined against consumption. Cleanup kernel re-zeroes entries for replay.

#define BB 16
#define TT 4096
#define HH 1024
#define CC 128
#define LL (TT / CC)          // 32 steps per chunk
#define NCH (BB * HH)         // 16384 channels
#define NCOL (NCH / 128)      // 128 block-columns
#define NPAIR ((CC - 1) * NCH)

__device__ unsigned long long g_pair[NPAIR];   // zero-init (.bss)

__device__ __forceinline__ unsigned long long pack2(float x, float y) {
    return (unsigned long long)__float_as_uint(x) |
           ((unsigned long long)__float_as_uint(y) << 32);
}
__device__ __forceinline__ float2 unpack2(unsigned long long u) {
    return make_float2(__uint_as_float((unsigned)u),
                       __uint_as_float((unsigned)(u >> 32)));
}
__device__ __forceinline__ unsigned long long ld_pair(const unsigned long long* p) {
    unsigned long long u;
    asm volatile("ld.relaxed.gpu.global.b64 %0, [%1];" : "=l"(u) : "l"(p) : "memory");
    return u;
}
__device__ __forceinline__ void st_pair(unsigned long long* p, unsigned long long u) {
    asm volatile("st.relaxed.gpu.global.b64 [%0], %1;" :: "l"(p), "l"(u) : "memory");
}

__global__ void __launch_bounds__(128, 6)
minrnn_lookback_kernel(const float* __restrict__ lc,   // (B, T, H)
                       const float* __restrict__ lv,   // (B, T+1, H)
                       float* __restrict__ out)        // (B, T, H)
{
    const int chunk = blockIdx.x >> 7;            // chunk-major ordering
    const int col   = blockIdx.x & 127;
    const int ch    = col * 128 + threadIdx.x;    // channel 0..16383
    const int b     = ch >> 10;
    const int h     = ch & (HH - 1);
    const int s0    = chunk * LL;

    const float* lcp  = lc + b * (TT * HH) + s0 * HH + h;
    const float* lvp2 = lv + b * ((TT + 1) * HH) + (s0 + 1) * HH + h;
    float*       op   = out + b * (TT * HH) + s0 * HH + h;

    // ---- Phase 1: load whole chunk (64 independent LDGs, max MLP) ----
    float cc[LL], vv[LL];
#pragma unroll
    for (int i = 0; i < LL; i++) {
        cc[i] = __ldcs(lcp + i * HH);
        vv[i] = __ldcs(lvp2 + i * HH);
    }

    // ---- Phase 2: carry-independent local scan. cc[i]<-A_i, vv[i]<-B_i ----
    float A = 1.0f, Bv = 0.0f;
#pragma unroll
    for (int i = 0; i < LL; i++) {
        const float e = __expf(cc[i]);
        A *= e;
        Bv = fmaf(e, Bv, __expf(vv[i]));
        cc[i] = A;
        vv[i] = Bv;
    }

    unsigned long long* mine = &g_pair[chunk * NCH + ch];
    const unsigned long long* base = g_pair + ch;          // stride NCH

    // ---- Phase 3: publish local AGGREGATE immediately (no waiting) ----
    if (chunk > 0 && chunk < CC - 1) {
        st_pair(mine, pack2(A, Bv));
    }

    // ---- Phase 4: resolve incoming state h_in via per-lane lookback ----
    float h_in;
    if (chunk == 0) {
        h_in = __expf(__ldg(lv + b * ((TT + 1) * HH) + h));   // exp(lv[b,0,h])
    } else {
        float Aacc = 1.0f, Bacc = 0.0f;
        int p = chunk - 1;
        unsigned long long u = ld_pair(base + (size_t)p * NCH);
        for (;;) {
            if (u == 0ull) {                       // not yet published
                __nanosleep(20);
                u = ld_pair(base + (size_t)p * NCH);
                continue;
            }
            const float2 e = unpack2(u);
            if (e.x == 0.0f) {                     // INCLUSIVE: e.y = h_end_p
                h_in = fmaf(Aacc, e.y, Bacc);
                break;
            }
            // AGGREGATE at p implies p >= 1 (chunk 0 only ever publishes INC),
            // so prefetching p-1 is always in-bounds.
            const unsigned long long un = ld_pair(base + (size_t)(p - 1) * NCH);
            Bacc = fmaf(Aacc, e.y, Bacc);
            Aacc *= e.x;
            p--;
            u = un;
        }
    }

    // ---- Phase 5: upgrade own entry to INCLUSIVE (shortens others' walks) --
    if (chunk < CC - 1) {
        st_pair(mine, pack2(0.0f, fmaf(A, h_in, Bv)));
    }

    // ---- Phase 6: fixup + store (independent) ----
#pragma unroll
    for (int i = 0; i < LL; i++) {
        __stcs(op + i * HH, fmaf(cc[i], h_in, vv[i]));
    }
}

// Re-zero descriptors so the next graph replay starts clean.
__global__ void minrnn_cleanup_kernel()
{
    const int i = blockIdx.x * blockDim.x + threadIdx.x;
    if (i < NPAIR) g_pair[i] = 0ull;
}

extern "C" void kernel_launch(void* const* d_in, const int* in_sizes, int n_in,
                              void* d_out, int out_size)
{
    const float* log_coeffs = (const float*)d_in[0];   // (B, T, H)
    const float* log_values = (const float*)d_in[1];   // (B, T+1, H)
    float*       out        = (float*)d_out;           // (B, T, H)

    const int blocks = CC * NCOL;      // 128 * 128 = 16384, chunk-major
    minrnn_lookback_kernel<<<blocks, 128>>>(log_coeffs, log_values, out);

    minrnn_cleanup_kernel<<<(NPAIR + 255) / 256, 256>>>();
}

// round 9
// speedup vs baseline: 3.2960x; 1.0285x over previous
#include <cuda_runtime.h>

// MinimalRNN scan: chunked A/B decomposition + payload-encoded decoupled
// lookback, float2-vectorized (2 channels per thread).
//   h_t = exp(lc[t-1]) * h_{t-1} + exp(lv[t]),  h_0 = exp(lv[0])
// Chunk-local: h_{s0+i} = A_i * h_in + B_i (carry-independent).
// Descriptor per (chunk, channel): u64 packed (A,B).
//   u == 0 -> unpublished (A>0, h_end>0 => never packs to 0; .bss valid)
//   A == 0 -> INCLUSIVE (B = h_end);  A > 0 -> AGGREGATE
// Relaxed 8B atomics; payload IS the flag (no fences). Cleanup kernel
// re-zeroes descriptors for graph replay (grid-stride, 16B stores).

#define BB 16
#define TT 4096
#define HH 1024
#define CC 128
#define LL (TT / CC)          // 32 steps per chunk
#define NCH (BB * HH)         // 16384 channels
#define NPR (NCH / 2)         // 8192 channel-pairs
#define NCOL (NPR / 128)      // 64 block-columns
#define NPAIR ((CC - 1) * NCH)

__device__ __align__(16) unsigned long long g_pair[NPAIR];   // .bss zero-init

__device__ __forceinline__ unsigned long long pack2(float x, float y) {
    return (unsigned long long)__float_as_uint(x) |
           ((unsigned long long)__float_as_uint(y) << 32);
}
__device__ __forceinline__ float2 unpack2(unsigned long long u) {
    return make_float2(__uint_as_float((unsigned)u),
                       __uint_as_float((unsigned)(u >> 32)));
}
__device__ __forceinline__ unsigned long long ld_pair(const unsigned long long* p) {
    unsigned long long u;
    asm volatile("ld.relaxed.gpu.global.b64 %0, [%1];" : "=l"(u) : "l"(p) : "memory");
    return u;
}
__device__ __forceinline__ void st_pair(unsigned long long* p, unsigned long long u) {
    asm volatile("st.relaxed.gpu.global.b64 [%0], %1;" :: "l"(p), "l"(u) : "memory");
}

__global__ void __launch_bounds__(128)
minrnn_lookback_kernel(const float* __restrict__ lc,   // (B, T, H)
                       const float* __restrict__ lv,   // (B, T+1, H)
                       float* __restrict__ out)        // (B, T, H)
{
    const int chunk = blockIdx.x >> 6;             // chunk-major (NCOL=64)
    const int col   = blockIdx.x & 63;
    const int pr    = col * 128 + threadIdx.x;     // channel-pair 0..8191
    const int ch    = pr * 2;                      // even channel of the pair
    const int b     = ch >> 10;
    const int h     = ch & (HH - 1);               // even -> float2 aligned
    const int s0    = chunk * LL;

    const float2* lcp  = (const float2*)(lc + b * (TT * HH) + s0 * HH + h);
    const float2* lvp2 = (const float2*)(lv + b * ((TT + 1) * HH) + (s0 + 1) * HH + h);
    float2*       op   = (float2*)(out + b * (TT * HH) + s0 * HH + h);
    const int     st2  = HH / 2;                   // float2 step stride

    // ---- Phase 1: load whole chunk (64 independent 8B LDGs) ----
    float2 cc[LL], vv[LL];
#pragma unroll
    for (int i = 0; i < LL; i++) {
        cc[i] = __ldcs(lcp + i * st2);
        vv[i] = __ldcs(lvp2 + i * st2);
    }

    // ---- Phase 2: carry-independent local scan (per channel) ----
    float A0 = 1.0f, B0 = 0.0f, A1 = 1.0f, B1 = 0.0f;
#pragma unroll
    for (int i = 0; i < LL; i++) {
        const float e0 = __expf(cc[i].x);
        const float e1 = __expf(cc[i].y);
        A0 *= e0;  B0 = fmaf(e0, B0, __expf(vv[i].x));
        A1 *= e1;  B1 = fmaf(e1, B1, __expf(vv[i].y));
        cc[i] = make_float2(A0, A1);
        vv[i] = make_float2(B0, B1);
    }

    unsigned long long* mine = &g_pair[chunk * NCH + ch];
    const unsigned long long* base = g_pair + ch;          // stride NCH

    // ---- Phase 3: publish local AGGREGATE immediately (no waiting) ----
    if (chunk > 0 && chunk < CC - 1) {
        st_pair(mine,     pack2(A0, B0));
        st_pair(mine + 1, pack2(A1, B1));
    }

    // ---- Phase 4: resolve incoming state via joint dual-channel lookback --
    float h_in0, h_in1;
    if (chunk == 0) {
        const float2 v0 = *(const float2*)(lv + b * ((TT + 1) * HH) + h);
        h_in0 = __expf(v0.x);
        h_in1 = __expf(v0.y);
    } else {
        float Aa0 = 1.0f, Ba0 = 0.0f, Aa1 = 1.0f, Ba1 = 0.0f;
        bool d0 = false, d1 = false;
        int p = chunk - 1;
        for (;;) {
            const unsigned long long* row = base + (size_t)p * NCH;
            unsigned long long u0 = d0 ? 1ull : ld_pair(row);
            unsigned long long u1 = d1 ? 1ull : ld_pair(row + 1);
            if (u0 == 0ull || u1 == 0ull) { __nanosleep(20); continue; }
            if (!d0) {
                const float2 e = unpack2(u0);
                if (e.x == 0.0f) { h_in0 = fmaf(Aa0, e.y, Ba0); d0 = true; }
                else { Ba0 = fmaf(Aa0, e.y, Ba0); Aa0 *= e.x; }
            }
            if (!d1) {
                const float2 e = unpack2(u1);
                if (e.x == 0.0f) { h_in1 = fmaf(Aa1, e.y, Ba1); d1 = true; }
                else { Ba1 = fmaf(Aa1, e.y, Ba1); Aa1 *= e.x; }
            }
            if (d0 && d1) break;
            p--;            // AGG implies p >= 1 (chunk 0 only publishes INC)
        }
    }

    // ---- Phase 5: upgrade own entry to INCLUSIVE (shortens others' walks) --
    if (chunk < CC - 1) {
        st_pair(mine,     pack2(0.0f, fmaf(A0, h_in0, B0)));
        st_pair(mine + 1, pack2(0.0f, fmaf(A1, h_in1, B1)));
    }

    // ---- Phase 6: fixup + store (independent, 32 8B STGs) ----
#pragma unroll
    for (int i = 0; i < LL; i++) {
        __stcs(op + i * st2, make_float2(fmaf(cc[i].x, h_in0, vv[i].x),
                                         fmaf(cc[i].y, h_in1, vv[i].y)));
    }
}

// Re-zero descriptors (grid-stride, 16B stores) for the next graph replay.
__global__ void minrnn_cleanup_kernel()
{
    ulonglong2* p = (ulonglong2*)g_pair;
    const int n = NPAIR / 2;
    for (int i = blockIdx.x * blockDim.x + threadIdx.x; i < n;
         i += gridDim.x * blockDim.x) {
        p[i] = make_ulonglong2(0ull, 0ull);
    }
}

extern "C" void kernel_launch(void* const* d_in, const int* in_sizes, int n_in,
                              void* d_out, int out_size)
{
    const float* log_coeffs = (const float*)d_in[0];   // (B, T, H)
    const float* log_values = (const float*)d_in[1];   // (B, T+1, H)
    float*       out        = (float*)d_out;           // (B, T, H)

    const int blocks = CC * NCOL;      // 128 * 64 = 8192, chunk-major
    minrnn_lookback_kernel<<<blocks, 128>>>(log_coeffs, log_values, out);

    minrnn_cleanup_kernel<<<1024, 256>>>();
}